// round 4
// baseline (speedup 1.0000x reference)
#include <cuda_runtime.h>
#include <math.h>

// Problem constants: NS = NT = 80, D = 512, N = 6400, kdiag = 79*79 = 6241.
#define NSd   80
#define Dd    512
#define Nn    6400
#define NB    64

// ---------------- device scratch (no allocation allowed) ----------------
__device__ float g_e1[NSd * Dd];
__device__ float g_e2[NSd * Dd];
__device__ float g_m1[NSd * Dd];
__device__ float g_m2[NSd * Dd];
__device__ float g_x1[NSd * Dd];
__device__ float g_x2[NSd * Dd];
__device__ float g_y1[NSd * Dd];   // becomes e1n after normalize
__device__ float g_y2[NSd * Dd];   // becomes e2n after normalize
__device__ float g_Mp0[NSd * NSd];
__device__ float g_v[Nn];          // v[p] = Mp[p%80, p/80]

__device__ __forceinline__ float warp_sum(float s) {
#pragma unroll
    for (int o = 16; o > 0; o >>= 1) s += __shfl_xor_sync(0xffffffffu, s, o);
    return s;
}

// ---------------- phase 1: small embedding chain ----------------

// e1[i,d] = U_src[0, d, i]; e2 likewise.
__global__ void k_transpose(const float* __restrict__ us, const float* __restrict__ ut) {
    int idx = blockIdx.x * blockDim.x + threadIdx.x;
    if (idx < NSd * Dd) {
        int i = idx >> 9, d = idx & 511;
        g_e1[idx] = us[d * NSd + i];
        g_e2[idx] = ut[d * NSd + i];
    }
}

// Mp0 = e1 @ e2.T + iou
__global__ void k_mp0(const float* __restrict__ iou) {
    int i = blockIdx.x;
    int warp = threadIdx.x >> 5, lane = threadIdx.x & 31;
    const float* a = g_e1 + i * Dd;
    for (int j = warp; j < NSd; j += 4) {
        const float* b = g_e2 + j * Dd;
        float s = 0.f;
#pragma unroll 4
        for (int d = lane; d < Dd; d += 32) s += a[d] * b[d];
        s = warp_sum(s);
        if (lane == 0) g_Mp0[i * NSd + j] = s + iou[i * NSd + j];
    }
}

// m1 = Mp0 @ e2 (which=0), m2 = Mp0.T @ e1 (which=1).  blockDim = 512.
__global__ void k_m1m2() {
    int r = blockIdx.x, which = blockIdx.y;
    __shared__ float w[NSd];
    int tid = threadIdx.x;
    if (tid < NSd) w[tid] = (which == 0) ? g_Mp0[r * NSd + tid] : g_Mp0[tid * NSd + r];
    __syncthreads();
    const float* E = (which == 0) ? g_e2 : g_e1;
    float* out     = (which == 0) ? g_m1 : g_m2;
    float acc = 0.f;
#pragma unroll 8
    for (int t = 0; t < NSd; t++) acc += w[t] * E[t * Dd + tid];
    out[r * Dd + tid] = acc;
}

// lam = ||e|| / ||m||; x = e + lam*m.  blockDim = 256, grid (80,2).
__global__ void k_lamprep() {
    int r = blockIdx.x, which = blockIdx.y;
    const float* e = ((which == 0) ? g_e1 : g_e2) + r * Dd;
    const float* m = ((which == 0) ? g_m1 : g_m2) + r * Dd;
    float* x       = ((which == 0) ? g_x1 : g_x2) + r * Dd;
    float se = 0.f, sm = 0.f;
    for (int d = threadIdx.x; d < Dd; d += 256) {
        float ev = e[d], mv = m[d];
        se += ev * ev; sm += mv * mv;
    }
    se = warp_sum(se); sm = warp_sum(sm);
    __shared__ float rs[8], rm[8], lamS;
    int warp = threadIdx.x >> 5, lane = threadIdx.x & 31;
    if (lane == 0) { rs[warp] = se; rm[warp] = sm; }
    __syncthreads();
    if (threadIdx.x == 0) {
        float SE = 0.f, SM = 0.f;
        for (int t = 0; t < 8; t++) { SE += rs[t]; SM += rm[t]; }
        lamS = sqrtf(SE) / sqrtf(SM);
    }
    __syncthreads();
    float lam = lamS;
    for (int d = threadIdx.x; d < Dd; d += 256) x[d] = e[d] + lam * m[d];
}

// y = relu(x @ W.T + b).  block per (row i, which). 128 threads, warp per output.
__global__ void k_gemmW(const float* __restrict__ W, const float* __restrict__ b) {
    int i = blockIdx.x, which = blockIdx.y;
    const float* X = ((which == 0) ? g_x1 : g_x2) + i * Dd;
    float* Y       = ((which == 0) ? g_y1 : g_y2) + i * Dd;
    __shared__ float xs[Dd];
    for (int d = threadIdx.x; d < Dd; d += 128) xs[d] = X[d];
    __syncthreads();
    int warp = threadIdx.x >> 5, lane = threadIdx.x & 31;
    for (int o = warp; o < Dd; o += 4) {
        const float* wr = W + o * Dd;
        float s = 0.f;
#pragma unroll 4
        for (int d = lane; d < Dd; d += 32) s += xs[d] * wr[d];
        s = warp_sum(s);
        if (lane == 0) Y[o] = fmaxf(s + b[o], 0.f);
    }
}

// row l2 normalize in place (eps = 1e-12)
__global__ void k_norm() {
    int r = blockIdx.x, which = blockIdx.y;
    float* y = ((which == 0) ? g_y1 : g_y2) + r * Dd;
    float s = 0.f;
    for (int d = threadIdx.x; d < Dd; d += 256) { float v = y[d]; s += v * v; }
    s = warp_sum(s);
    __shared__ float rs[8]; __shared__ float invS;
    int warp = threadIdx.x >> 5, lane = threadIdx.x & 31;
    if (lane == 0) rs[warp] = s;
    __syncthreads();
    if (threadIdx.x == 0) {
        float S = 0.f;
        for (int t = 0; t < 8; t++) S += rs[t];
        invS = 1.0f / fmaxf(sqrtf(S), 1e-12f);
    }
    __syncthreads();
    float inv = invS;
    for (int d = threadIdx.x; d < Dd; d += 256) y[d] *= inv;
}

// Mp = e1n @ e2n.T ; thr_flag ; v[p] = Mp[s,t] with p = t*80+s
__global__ void k_mp_thr(float* __restrict__ Mp_out, float* __restrict__ flag_out,
                         const float* __restrict__ kf, const float* __restrict__ iou,
                         const float* __restrict__ thrp) {
    int i = blockIdx.x;
    int warp = threadIdx.x >> 5, lane = threadIdx.x & 31;
    const float* a = g_y1 + i * Dd;
    float th = thrp[0];
    for (int j = warp; j < NSd; j += 4) {
        const float* b = g_y2 + j * Dd;
        float s = 0.f;
#pragma unroll 4
        for (int d = lane; d < Dd; d += 32) s += a[d] * b[d];
        s = warp_sum(s);
        if (lane == 0) {
            Mp_out[i * NSd + j] = s;
            g_v[j * NSd + i] = s;
            float fl = (kf[i * NSd + j] == -1.0f || iou[i * NSd + j] == 0.0f || s < th) ? 1.0f : 0.0f;
            flag_out[i * NSd + j] = fl;
        }
    }
}

// ---------------- phase 2: build A directly into the L output region ----------------
// A[p,q] = 6241 (p==q); -0.5*(v[p]+v[q]) if (s1!=s2 && t1!=t2) and q<p; upper triangle = 0.
__global__ void k_buildA(float* __restrict__ L) {
    int p = blockIdx.x;
    int s1 = p % NSd, t1 = p / NSd;
    float vp = g_v[p];
    float* row = L + (size_t)p * Nn;
    for (int q = threadIdx.x; q < Nn; q += 256) {
        float val = 0.f;
        if (q == p) val = 6241.0f;
        else if (q < p) {
            int s2 = q % NSd, t2 = q / NSd;
            if (s1 != s2 && t1 != t2) val = -0.5f * (vp + g_v[q]);
        }
        row[q] = val;
    }
}

// ---------------- phase 3: blocked Cholesky (in place, lower) ----------------

// Factor 64x64 diagonal block at (j,j). One block, 256 threads.
__global__ __launch_bounds__(256) void potf2_k(float* __restrict__ L, int j) {
    __shared__ float sh[64 * 65];
    int tid = threadIdx.x;
    float* A = L + (size_t)j * Nn + j;
    for (int idx = tid; idx < 64 * 64; idx += 256) {
        int r = idx >> 6, c = idx & 63;
        sh[r * 65 + c] = A[(size_t)r * Nn + c];
    }
    __syncthreads();
    for (int c = 0; c < 64; c++) {
        float scc = sh[c * 65 + c];
        float dv = sqrtf(scc);
        float inv = 1.0f / dv;
        __syncthreads();                       // everyone has read scc
        if (tid == 0) sh[c * 65 + c] = dv;
        for (int r = c + 1 + tid; r < 64; r += 256) sh[r * 65 + c] *= inv;
        __syncthreads();                       // column scaled
        int m = 63 - c;
        for (int idx = tid; idx < m * m; idx += 256) {
            int rr = idx / m;
            int qq = idx - rr * m;
            rr += c + 1; qq += c + 1;
            sh[rr * 65 + qq] -= sh[rr * 65 + c] * sh[qq * 65 + c];
        }
        __syncthreads();                       // trailing updated before next read
    }
    for (int idx = tid; idx < 64 * 64; idx += 256) {
        int r = idx >> 6, c = idx & 63;
        if (c <= r) A[(size_t)r * Nn + c] = sh[r * 65 + c];
    }
}

// Panel solve: rows j+64 .. j+64+M-1, X * Ld^T = A_panel. Thread per row,
// x[] fully register-resident via complete unrolling.
__global__ __launch_bounds__(256) void trsm_k(float* __restrict__ L, int j, int M) {
    __shared__ float Ld[64 * 65];
    __shared__ float invd[64];
    int tid = threadIdx.x;
    const float* D = L + (size_t)j * Nn + j;
    for (int idx = tid; idx < 64 * 64; idx += 256) {
        int r = idx >> 6, c = idx & 63;
        Ld[r * 65 + c] = D[(size_t)r * Nn + c];
    }
    __syncthreads();
    if (tid < 64) invd[tid] = 1.0f / Ld[tid * 65 + tid];
    __syncthreads();
    int ri = blockIdx.x * 256 + tid;
    if (ri >= M) return;
    float* row = L + (size_t)(j + NB + ri) * Nn + j;
    float x[64];
#pragma unroll
    for (int c4 = 0; c4 < 16; c4++) {
        float4 t = *(const float4*)(row + c4 * 4);
        x[c4 * 4 + 0] = t.x; x[c4 * 4 + 1] = t.y; x[c4 * 4 + 2] = t.z; x[c4 * 4 + 3] = t.w;
    }
#pragma unroll
    for (int c = 0; c < 64; c++) {
        float s = x[c];
#pragma unroll
        for (int k = 0; k < 64; k++)
            if (k < c) s -= x[k] * Ld[c * 65 + k];
        x[c] = s * invd[c];
    }
#pragma unroll
    for (int c4 = 0; c4 < 16; c4++) {
        float4 t;
        t.x = x[c4 * 4 + 0]; t.y = x[c4 * 4 + 1]; t.z = x[c4 * 4 + 2]; t.w = x[c4 * 4 + 3];
        *(float4*)(row + c4 * 4) = t;
    }
}

// Trailing update: C -= P * P^T, P = [M x 64] panel, lower block tiles only.
// 128x128 tile per block, 8x8 per thread.
__global__ __launch_bounds__(256) void syrk_k(float* __restrict__ L, int j, int M) {
    int bx = blockIdx.x, by = blockIdx.y;
    if (by < bx) return;
    const float* __restrict__ P = L + (size_t)(j + NB) * Nn + j;
    float* __restrict__ C = L + (size_t)(j + NB) * Nn + (j + NB);
    int row0 = by * 128, col0 = bx * 128;
    __shared__ float As[16][132];
    __shared__ float Bs[16][132];
    int tid = threadIdx.x;
    float acc[8][8];
#pragma unroll
    for (int u = 0; u < 8; u++)
#pragma unroll
        for (int v = 0; v < 8; v++) acc[u][v] = 0.f;

    int ty = tid >> 4, tx = tid & 15;
    int rr = ty * 8, cc = tx * 8;

    for (int kk = 0; kk < NB; kk += 16) {
#pragma unroll
        for (int rep = 0; rep < 2; rep++) {
            int f4 = tid + rep * 256;
            int i = f4 >> 2;
            int k4 = (f4 & 3) << 2;
            float4 av = make_float4(0.f, 0.f, 0.f, 0.f);
            float4 bv = make_float4(0.f, 0.f, 0.f, 0.f);
            if (row0 + i < M) av = *(const float4*)(P + (size_t)(row0 + i) * Nn + kk + k4);
            if (col0 + i < M) bv = *(const float4*)(P + (size_t)(col0 + i) * Nn + kk + k4);
            As[k4 + 0][i] = av.x; As[k4 + 1][i] = av.y; As[k4 + 2][i] = av.z; As[k4 + 3][i] = av.w;
            Bs[k4 + 0][i] = bv.x; Bs[k4 + 1][i] = bv.y; Bs[k4 + 2][i] = bv.z; Bs[k4 + 3][i] = bv.w;
        }
        __syncthreads();
#pragma unroll
        for (int k = 0; k < 16; k++) {
            float a[8], bq[8];
            *(float4*)&a[0]  = *(const float4*)&As[k][rr];
            *(float4*)&a[4]  = *(const float4*)&As[k][rr + 4];
            *(float4*)&bq[0] = *(const float4*)&Bs[k][cc];
            *(float4*)&bq[4] = *(const float4*)&Bs[k][cc + 4];
#pragma unroll
            for (int u = 0; u < 8; u++)
#pragma unroll
                for (int v = 0; v < 8; v++) acc[u][v] += a[u] * bq[v];
        }
        __syncthreads();
    }

    if (by > bx) {
        // strictly below diagonal: every element is in the lower triangle
#pragma unroll
        for (int u = 0; u < 8; u++) {
            int gr = row0 + rr + u;
            if (gr < M) {
                float* cp = C + (size_t)gr * Nn + col0 + cc;
                float4 c0 = *(float4*)cp;
                float4 c1 = *(float4*)(cp + 4);
                c0.x -= acc[u][0]; c0.y -= acc[u][1]; c0.z -= acc[u][2]; c0.w -= acc[u][3];
                c1.x -= acc[u][4]; c1.y -= acc[u][5]; c1.z -= acc[u][6]; c1.w -= acc[u][7];
                *(float4*)cp = c0;
                *(float4*)(cp + 4) = c1;
            }
        }
    } else {
        // diagonal tile: keep upper triangle untouched (it holds the output zeros)
#pragma unroll
        for (int u = 0; u < 8; u++) {
            int gr = row0 + rr + u;
            if (gr < M) {
#pragma unroll
                for (int v = 0; v < 8; v++) {
                    int gc = col0 + cc + v;
                    if (gc <= gr) C[(size_t)gr * Nn + gc] -= acc[u][v];
                }
            }
        }
    }
}

// ---------------- launch ----------------
extern "C" void kernel_launch(void* const* d_in, const int* in_sizes, int n_in,
                              void* d_out, int out_size) {
    (void)in_sizes; (void)n_in; (void)out_size;
    const float* U_src = (const float*)d_in[0];
    const float* U_tgt = (const float*)d_in[1];
    const float* kf    = (const float*)d_in[2];
    const float* thrp  = (const float*)d_in[3];
    const float* iou   = (const float*)d_in[4];
    const float* W     = (const float*)d_in[5];
    const float* b     = (const float*)d_in[6];
    // inputs 7..10 (start/end index grids) encode the fully-connected structure,
    // which is folded analytically into k_buildA.

    float* out      = (float*)d_out;
    float* Mp_out   = out;                       // [80*80]
    float* Lm       = out + NSd * NSd;           // [6400*6400]
    float* flag_out = out + NSd * NSd + Nn * Nn; // [80*80]

    k_transpose<<<(NSd * Dd + 255) / 256, 256>>>(U_src, U_tgt);
    k_mp0<<<NSd, 128>>>(iou);
    k_m1m2<<<dim3(NSd, 2), 512>>>();
    k_lamprep<<<dim3(NSd, 2), 256>>>();
    k_gemmW<<<dim3(NSd, 2), 128>>>(W, b);
    k_norm<<<dim3(NSd, 2), 256>>>();
    k_mp_thr<<<NSd, 128>>>(Mp_out, flag_out, kf, iou, thrp);
    k_buildA<<<Nn, 256>>>(Lm);

    for (int j = 0; j < Nn; j += NB) {
        potf2_k<<<1, 256>>>(Lm, j);
        int M = Nn - j - NB;
        if (M > 0) {
            trsm_k<<<(M + 255) / 256, 256>>>(Lm, j, M);
            dim3 g((M + 127) / 128, (M + 127) / 128);
            syrk_k<<<g, 256>>>(Lm, j, M);
        }
    }
}